// round 9
// baseline (speedup 1.0000x reference)
#include <cuda_runtime.h>

// Problem constants
#define BB   4
#define NPTS 16384
#define MPTS 4096
#define CCH  256

typedef unsigned long long ull;

// Scratch (device globals; no allocation allowed)
__device__ float g_zT[(size_t)BB * MPTS * CCH];   // [b][m][o]
__device__ float g_y1[(size_t)BB * CCH * NPTS];   // [b][o][n]
__device__ float g_w [(size_t)BB * NPTS * 4];
__device__ int   g_idx[(size_t)BB * NPTS * 4];
__device__ float g_WT1a[CCH * CCH];               // W1[:,0:C]   transposed -> [k][o]
__device__ float g_WT1b[CCH * CCH];               // W1[:,C:2C]  transposed -> [k][o]
__device__ float g_WT2 [CCH * CCH];               // W2          transposed -> [k][o]

__device__ __forceinline__ void cp_async16(void* smem_dst, const void* gmem_src) {
    unsigned s = (unsigned)__cvta_generic_to_shared(smem_dst);
    asm volatile("cp.async.cg.shared.global [%0], [%1], 16;\n" :: "r"(s), "l"(gmem_src));
}
#define CP_COMMIT() asm volatile("cp.async.commit_group;\n" ::: "memory")
#define CP_WAIT0()  asm volatile("cp.async.wait_group 0;\n" ::: "memory")

// ---- packed f32x2 FMA (single fused op per lane; per-lane rn rounding is
//      identical to the scalar FFMA chain -> bit-exact vs verified kernel) ----
__device__ __forceinline__ void ffma2(ull& c, ull a, ull b) {
    asm("fma.rn.f32x2 %0, %1, %2, %0;" : "+l"(c) : "l"(a), "l"(b));
}
__device__ __forceinline__ ull pack2(float lo, float hi) {
    ull r;
    asm("mov.b64 %0, {%1, %2};" : "=l"(r) : "f"(lo), "f"(hi));
    return r;
}
__device__ __forceinline__ float2 unpack2(ull v) {
    float lo, hi;
    asm("mov.b64 {%0, %1}, %2;" : "=f"(lo), "=f"(hi) : "l"(v));
    return make_float2(lo, hi);
}

extern __shared__ float sm_f[];

// ---------------------------------------------------------------------------
// Weight transpose (runs once per launch, trivial cost).
// ---------------------------------------------------------------------------
__global__ void __launch_bounds__(256) transpose_w_kernel(
    const float* __restrict__ W1, const float* __restrict__ W2)
{
    int k = blockIdx.x;
    int o = threadIdx.x;
    g_WT1a[k * CCH + o] = W1[(size_t)o * (2 * CCH) + k];
    g_WT1b[k * CCH + o] = W1[(size_t)o * (2 * CCH) + CCH + k];
    g_WT2 [k * CCH + o] = W2[(size_t)o * CCH + k];
}

// ---------------------------------------------------------------------------
// kNN body: VERIFIED bit-exact scalar version (rel_err 7.2e-6 in R6).
// Per-op fp32 rounding via __f*_rn intrinsics (contraction-proof by spec).
// 4x unrolled with min-gate; insert chain in ascending index order with
// strict '<' — identical to jax top_k semantics. DO NOT pack this math:
// packed mul/add f32x2 gets FMA-contracted and flips near-tie neighbors.
// ---------------------------------------------------------------------------
__device__ __forceinline__ void knn_body(const float* __restrict__ p1,
                                         const float* __restrict__ p2,
                                         int tile, int b)
{
    float* sx = sm_f;
    float* sy = sm_f + MPTS;
    float* sz = sm_f + 2 * MPTS;
    float* ss = sm_f + 3 * MPTS;
    const float* P2 = p2 + (size_t)b * MPTS * 3;
    for (int i = threadIdx.x; i < MPTS; i += 256) {
        float x = P2[i * 3 + 0];
        float y = P2[i * 3 + 1];
        float z = P2[i * 3 + 2];
        sx[i] = x; sy[i] = y; sz[i] = z;
        ss[i] = __fadd_rn(__fadd_rn(__fmul_rn(x, x), __fmul_rn(y, y)),
                          __fmul_rn(z, z));
    }
    __syncthreads();

    int n = tile * 256 + threadIdx.x;
    const float* q = p1 + ((size_t)b * NPTS + n) * 3;
    float px = q[0], py = q[1], pz = q[2];
    float s1 = __fadd_rn(__fadd_rn(__fmul_rn(px, px), __fmul_rn(py, py)),
                         __fmul_rn(pz, pz));

    float d0 = 3.4e38f, d1 = 3.4e38f, d2 = 3.4e38f;
    int   i0 = 0, i1 = 0, i2 = 0;
    for (int m = 0; m < MPTS; m += 4) {
        float dv[4];
#pragma unroll
        for (int u = 0; u < 4; ++u) {
            float dot = __fadd_rn(__fadd_rn(__fmul_rn(px, sx[m + u]),
                                            __fmul_rn(py, sy[m + u])),
                                  __fmul_rn(pz, sz[m + u]));
            float d = __fadd_rn(s1, ss[m + u]);
            d = __fsub_rn(d, __fmul_rn(2.0f, dot));
            dv[u] = fmaxf(d, 0.0f);
        }
        float mn = fminf(fminf(dv[0], dv[1]), fminf(dv[2], dv[3]));
        if (mn < d2) {
#pragma unroll
            for (int u = 0; u < 4; ++u) {
                float d = dv[u];
                if (d < d2) {
                    if (d < d1) {
                        if (d < d0) { d2 = d1; i2 = i1; d1 = d0; i1 = i0; d0 = d; i0 = m + u; }
                        else        { d2 = d1; i2 = i1; d1 = d;  i1 = m + u; }
                    } else          { d2 = d;  i2 = m + u; }
                }
            }
        }
    }
    float r0 = __fdiv_rn(1.0f, __fadd_rn(d0, 1e-8f));
    float r1 = __fdiv_rn(1.0f, __fadd_rn(d1, 1e-8f));
    float r2 = __fdiv_rn(1.0f, __fadd_rn(d2, 1e-8f));
    float sum = __fadd_rn(__fadd_rn(r0, r1), r2);
    size_t base = ((size_t)b * NPTS + n) * 4;
    g_w[base + 0] = __fdiv_rn(r0, sum);
    g_w[base + 1] = __fdiv_rn(r1, sum);
    g_w[base + 2] = __fdiv_rn(r2, sum);
    g_w[base + 3] = 0.f;
    g_idx[base + 0] = i0; g_idx[base + 1] = i1; g_idx[base + 2] = i2; g_idx[base + 3] = 0;
}

// ---------------------------------------------------------------------------
// SGEMM 128x128, kTile=32, double-buffered cp.async both operands.
// Inner loop uses fma.rn.f32x2: acc pairs along the o-dim (adjacent in As ->
// 64-bit shared loads, no pack), b values lane-duplicated (8 packs / kk).
// Per-element accumulation order identical to verified scalar kernel.
// ---------------------------------------------------------------------------
template <int MODE>
__device__ __forceinline__ void gemm_body(
    const float* __restrict__ AT,          // [K][CCH] transposed weights
    const float* __restrict__ Bp, int ldb, int K,
    const float* __restrict__ bias,
    float* __restrict__ Op, int ldn,
    int n0, int o0, int b)
{
    float (*As)[32][128] = (float(*)[32][128])sm_f;                 // 32KB
    float (*Bs)[32][128] = (float(*)[32][128])(sm_f + 2 * 32 * 128);

    int tid = threadIdx.x;
    int tx = tid & 15;
    int ty = tid >> 4;

    int ck[4], cc[4];
#pragma unroll
    for (int i = 0; i < 4; ++i) {
        int f = tid + 256 * i;
        ck[i] = f >> 5;
        cc[i] = (f & 31) * 4;
    }

    ull acc2[4][8];
#pragma unroll
    for (int i = 0; i < 4; ++i)
#pragma unroll
        for (int j = 0; j < 8; ++j) acc2[i][j] = 0ull;

    // prologue: stage 0
#pragma unroll
    for (int i = 0; i < 4; ++i) {
        cp_async16(&As[0][ck[i]][cc[i]], AT + (size_t)ck[i] * CCH + o0 + cc[i]);
        cp_async16(&Bs[0][ck[i]][cc[i]], Bp + (size_t)ck[i] * ldb + n0 + cc[i]);
    }
    CP_COMMIT();
    CP_WAIT0();
    __syncthreads();

    int cur = 0;
    for (int k0 = 0; k0 < K; k0 += 32) {
        bool nxt = (k0 + 32) < K;
        if (nxt) {
            int nb = cur ^ 1;
#pragma unroll
            for (int i = 0; i < 4; ++i) {
                cp_async16(&As[nb][ck[i]][cc[i]],
                           AT + (size_t)(k0 + 32 + ck[i]) * CCH + o0 + cc[i]);
                cp_async16(&Bs[nb][ck[i]][cc[i]],
                           Bp + (size_t)(k0 + 32 + ck[i]) * ldb + n0 + cc[i]);
            }
            CP_COMMIT();
        }
#pragma unroll
        for (int kk = 0; kk < 32; ++kk) {
            ull aa[4];
            aa[0] = *(const ull*)&As[cur][kk][ty * 4];          // o pair (0,1)
            aa[1] = *(const ull*)&As[cur][kk][ty * 4 + 2];      // o pair (2,3)
            aa[2] = *(const ull*)&As[cur][kk][ty * 4 + 64];     // o pair (4,5)
            aa[3] = *(const ull*)&As[cur][kk][ty * 4 + 66];     // o pair (6,7)
            float4 y0 = *(const float4*)&Bs[cur][kk][tx * 4];
            float4 y1 = *(const float4*)&Bs[cur][kk][tx * 4 + 64];
            ull bb[8];
            bb[0] = pack2(y0.x, y0.x);
            bb[1] = pack2(y0.y, y0.y);
            bb[2] = pack2(y0.z, y0.z);
            bb[3] = pack2(y0.w, y0.w);
            bb[4] = pack2(y1.x, y1.x);
            bb[5] = pack2(y1.y, y1.y);
            bb[6] = pack2(y1.z, y1.z);
            bb[7] = pack2(y1.w, y1.w);
#pragma unroll
            for (int ip = 0; ip < 4; ++ip)
#pragma unroll
                for (int j = 0; j < 8; ++j)
                    ffma2(acc2[ip][j], aa[ip], bb[j]);
        }
        CP_WAIT0();
        __syncthreads();
        cur ^= 1;
    }

    // unpack to scalar acc[i][j] (i = o index within microtile, j = n index)
    float acc[8][8];
#pragma unroll
    for (int ip = 0; ip < 4; ++ip)
#pragma unroll
        for (int j = 0; j < 8; ++j) {
            float2 f = unpack2(acc2[ip][j]);
            acc[2 * ip + 0][j] = f.x;
            acc[2 * ip + 1][j] = f.y;
        }

    if (MODE == 0) {
#pragma unroll
        for (int j = 0; j < 8; ++j) {
            int m = n0 + ((j < 4) ? (tx * 4 + j) : (64 + tx * 4 + (j - 4)));
            size_t base = ((size_t)b * MPTS + m) * CCH + o0 + ty * 4;
            *(float4*)&g_zT[base]      = make_float4(acc[0][j], acc[1][j], acc[2][j], acc[3][j]);
            *(float4*)&g_zT[base + 64] = make_float4(acc[4][j], acc[5][j], acc[6][j], acc[7][j]);
        }
        return;
    }

    if (MODE == 1) {
#pragma unroll
        for (int j = 0; j < 8; ++j) {
            int n = n0 + ((j < 4) ? (tx * 4 + j) : (64 + tx * 4 + (j - 4)));
            size_t wb = ((size_t)b * NPTS + n) * 4;
            float4 w4 = *(const float4*)&g_w[wb];
            int4   i4 = *(const int4*)&g_idx[wb];
            float wk[3] = {w4.x, w4.y, w4.z};
            int   ik[3] = {i4.x, i4.y, i4.z};
#pragma unroll
            for (int t = 0; t < 3; ++t) {
                const float* zp = &g_zT[((size_t)b * MPTS + ik[t]) * CCH + o0 + ty * 4];
                float4 z0 = *(const float4*)zp;
                float4 z1 = *(const float4*)(zp + 64);
                acc[0][j] += wk[t] * z0.x;
                acc[1][j] += wk[t] * z0.y;
                acc[2][j] += wk[t] * z0.z;
                acc[3][j] += wk[t] * z0.w;
                acc[4][j] += wk[t] * z1.x;
                acc[5][j] += wk[t] * z1.y;
                acc[6][j] += wk[t] * z1.z;
                acc[7][j] += wk[t] * z1.w;
            }
        }
    }

#pragma unroll
    for (int i = 0; i < 8; ++i) {
        int o = o0 + ((i < 4) ? (ty * 4 + i) : (64 + ty * 4 + (i - 4)));
        float bv = bias[o];
        float4 v0, v1;
        v0.x = fmaxf(acc[i][0] + bv, 0.0f);
        v0.y = fmaxf(acc[i][1] + bv, 0.0f);
        v0.z = fmaxf(acc[i][2] + bv, 0.0f);
        v0.w = fmaxf(acc[i][3] + bv, 0.0f);
        v1.x = fmaxf(acc[i][4] + bv, 0.0f);
        v1.y = fmaxf(acc[i][5] + bv, 0.0f);
        v1.z = fmaxf(acc[i][6] + bv, 0.0f);
        v1.w = fmaxf(acc[i][7] + bv, 0.0f);
        size_t base = (size_t)o * ldn + n0 + tx * 4;
        *(float4*)&Op[base]      = v0;
        *(float4*)&Op[base + 64] = v1;
    }
}

// ---------------------------------------------------------------------------
// Fused launch: blocks [0,256) do kNN, blocks [256,512) do zGEMM (MODE 0).
// ---------------------------------------------------------------------------
__global__ void __launch_bounds__(256, 2) fused0_kernel(
    const float* __restrict__ p1, const float* __restrict__ p2,
    const float* __restrict__ f2)
{
    int bx = blockIdx.x;
    if (bx < (NPTS / 256) * BB) {
        knn_body(p1, p2, bx & 63, bx >> 6);
    } else {
        int i  = bx - (NPTS / 256) * BB;
        int nt = i & (MPTS / 128 - 1);
        int r  = i >> 5;
        int ot = r & 1;
        int b  = r >> 1;
        gemm_body<0>(g_WT1b, f2 + (size_t)b * CCH * MPTS, MPTS, CCH,
                     nullptr, nullptr, 0, nt * 128, ot * 128, b);
    }
}

__global__ void __launch_bounds__(256, 2) gemm1_kernel(
    const float* __restrict__ f1, const float* __restrict__ b1)
{
    int b = blockIdx.z;
    gemm_body<1>(g_WT1a, f1 + (size_t)b * CCH * NPTS, NPTS, CCH, b1,
                 g_y1 + (size_t)b * CCH * NPTS, NPTS,
                 blockIdx.x * 128, blockIdx.y * 128, b);
}

__global__ void __launch_bounds__(256, 2) gemm2_kernel(
    const float* __restrict__ b2, float* __restrict__ out)
{
    int b = blockIdx.z;
    gemm_body<2>(g_WT2, g_y1 + (size_t)b * CCH * NPTS, NPTS, CCH, b2,
                 out + (size_t)b * CCH * NPTS, NPTS,
                 blockIdx.x * 128, blockIdx.y * 128, b);
}

// ---------------------------------------------------------------------------
extern "C" void kernel_launch(void* const* d_in, const int* in_sizes, int n_in,
                              void* d_out, int out_size)
{
    const float* p1 = (const float*)d_in[0];
    const float* f1 = (const float*)d_in[1];
    const float* p2 = (const float*)d_in[2];
    const float* f2 = (const float*)d_in[3];
    const float* W1 = (const float*)d_in[4];
    const float* b1 = (const float*)d_in[5];
    const float* W2 = (const float*)d_in[6];
    const float* b2 = (const float*)d_in[7];
    float* out = (float*)d_out;

    const int GEMM_SMEM  = 2 * (2 * 32 * 128) * (int)sizeof(float); // 65536
    const int FUSED_SMEM = MPTS * 4 * (int)sizeof(float);           // 65536

    cudaFuncSetAttribute(fused0_kernel, cudaFuncAttributeMaxDynamicSharedMemorySize, FUSED_SMEM);
    cudaFuncSetAttribute(gemm1_kernel,  cudaFuncAttributeMaxDynamicSharedMemorySize, GEMM_SMEM);
    cudaFuncSetAttribute(gemm2_kernel,  cudaFuncAttributeMaxDynamicSharedMemorySize, GEMM_SMEM);

    // 0) transpose weights into [k][o] layout
    transpose_w_kernel<<<CCH, CCH>>>(W1, W2);

    // 1) kNN (256 blocks) + zGEMM (256 blocks) fused
    fused0_kernel<<<512, 256, FUSED_SMEM>>>(p1, p2, f2);

    // 2) y1 = relu(W1[:, 0:C] @ f1 + gather(zT) + b1)
    gemm1_kernel<<<dim3(NPTS / 128, CCH / 128, BB), 256, GEMM_SMEM>>>(f1, b1);

    // 3) out = relu(W2 @ y1 + b2)
    gemm2_kernel<<<dim3(NPTS / 128, CCH / 128, BB), 256, GEMM_SMEM>>>(b2, out);
}

// round 10
// speedup vs baseline: 1.0624x; 1.0624x over previous
#include <cuda_runtime.h>

// Problem constants
#define BB   4
#define NPTS 16384
#define MPTS 4096
#define CCH  256

typedef unsigned long long ull;

// Scratch (device globals; no allocation allowed)
__device__ float g_zT[(size_t)BB * MPTS * CCH];   // [b][m][o]
__device__ float g_y1[(size_t)BB * CCH * NPTS];   // [b][o][n]
__device__ float g_w [(size_t)BB * NPTS * 4];
__device__ int   g_idx[(size_t)BB * NPTS * 4];
__device__ float g_WT1a[CCH * CCH];               // W1[:,0:C]   transposed -> [k][o]
__device__ float g_WT1b[CCH * CCH];               // W1[:,C:2C]  transposed -> [k][o]
__device__ float g_WT2 [CCH * CCH];               // W2          transposed -> [k][o]

__device__ __forceinline__ void cp_async16(void* smem_dst, const void* gmem_src) {
    unsigned s = (unsigned)__cvta_generic_to_shared(smem_dst);
    asm volatile("cp.async.cg.shared.global [%0], [%1], 16;\n" :: "r"(s), "l"(gmem_src));
}
#define CP_COMMIT() asm volatile("cp.async.commit_group;\n" ::: "memory")
#define CP_WAIT0()  asm volatile("cp.async.wait_group 0;\n" ::: "memory")

// ---- packed f32x2 helpers ----
__device__ __forceinline__ void ffma2(ull& c, ull a, ull b) {
    asm("fma.rn.f32x2 %0, %1, %2, %0;" : "+l"(c) : "l"(a), "l"(b));
}
__device__ __forceinline__ ull fma2v(ull a, ull b, ull c) {
    ull r; asm("fma.rn.f32x2 %0, %1, %2, %3;" : "=l"(r) : "l"(a), "l"(b), "l"(c)); return r;
}
__device__ __forceinline__ ull mul2(ull a, ull b) {
    ull r; asm("mul.rn.f32x2 %0, %1, %2;" : "=l"(r) : "l"(a), "l"(b)); return r;
}
__device__ __forceinline__ ull add2(ull a, ull b) {
    ull r; asm("add.rn.f32x2 %0, %1, %2;" : "=l"(r) : "l"(a), "l"(b)); return r;
}
__device__ __forceinline__ ull pack2(float lo, float hi) {
    ull r;
    asm("mov.b64 %0, {%1, %2};" : "=l"(r) : "f"(lo), "f"(hi));
    return r;
}
__device__ __forceinline__ float2 unpack2(ull v) {
    float lo, hi;
    asm("mov.b64 {%0, %1}, %2;" : "=f"(lo), "=f"(hi) : "l"(v));
    return make_float2(lo, hi);
}

extern __shared__ float sm_f[];

// ---------------------------------------------------------------------------
// Weight transpose (runs once per launch, trivial cost).
// ---------------------------------------------------------------------------
__global__ void __launch_bounds__(256) transpose_w_kernel(
    const float* __restrict__ W1, const float* __restrict__ W2)
{
    int k = blockIdx.x;
    int o = threadIdx.x;
    g_WT1a[k * CCH + o] = W1[(size_t)o * (2 * CCH) + k];
    g_WT1b[k * CCH + o] = W1[(size_t)o * (2 * CCH) + CCH + k];
    g_WT2 [k * CCH + o] = W2[(size_t)o * CCH + k];
}

// ---------------------------------------------------------------------------
// kNN body. Selection must be bit-exact vs the XLA reference (per-op fp32
// rounding). Strategy: a FAST packed-f32x2 gate (contraction allowed —
// approximate, |fast-exact| <= ~3e-5) screens candidates against
// d2 + 1e-3 (30x safety margin: the gate can never miss a true insert).
// On gate hit, the 4 distances are recomputed with the VERIFIED bit-exact
// scalar __f*_rn sequence and the verified insert chain runs on those.
// ---------------------------------------------------------------------------
__device__ __forceinline__ void knn_body(const float* __restrict__ p1,
                                         const float* __restrict__ p2,
                                         int tile, int b)
{
    float* sx = sm_f;
    float* sy = sm_f + MPTS;
    float* sz = sm_f + 2 * MPTS;
    float* ss = sm_f + 3 * MPTS;
    const float* P2 = p2 + (size_t)b * MPTS * 3;
    for (int i = threadIdx.x; i < MPTS; i += 256) {
        float x = P2[i * 3 + 0];
        float y = P2[i * 3 + 1];
        float z = P2[i * 3 + 2];
        sx[i] = x; sy[i] = y; sz[i] = z;
        ss[i] = __fadd_rn(__fadd_rn(__fmul_rn(x, x), __fmul_rn(y, y)),
                          __fmul_rn(z, z));
    }
    __syncthreads();

    int n = tile * 256 + threadIdx.x;
    const float* q = p1 + ((size_t)b * NPTS + n) * 3;
    float px = q[0], py = q[1], pz = q[2];
    float s1 = __fadd_rn(__fadd_rn(__fmul_rn(px, px), __fmul_rn(py, py)),
                         __fmul_rn(pz, pz));
    ull qx2 = pack2(px, px);
    ull qy2 = pack2(py, py);
    ull qz2 = pack2(pz, pz);
    ull s12 = pack2(s1, s1);
    ull m22 = pack2(-2.0f, -2.0f);

    float d0 = 3.4e38f, d1 = 3.4e38f, d2 = 3.4e38f;
    int   i0 = 0, i1 = 0, i2 = 0;
    for (int m = 0; m < MPTS; m += 4) {
        // --- fast approximate gate (packed, contraction OK) ---
        ull xA = *(const ull*)&sx[m], xB = *(const ull*)&sx[m + 2];
        ull yA = *(const ull*)&sy[m], yB = *(const ull*)&sy[m + 2];
        ull zA = *(const ull*)&sz[m], zB = *(const ull*)&sz[m + 2];
        ull sA = *(const ull*)&ss[m], sB = *(const ull*)&ss[m + 2];
        ull dotA = fma2v(qz2, zA, fma2v(qy2, yA, mul2(qx2, xA)));
        ull dotB = fma2v(qz2, zB, fma2v(qy2, yB, mul2(qx2, xB)));
        ull dA = fma2v(m22, dotA, add2(s12, sA));
        ull dB = fma2v(m22, dotB, add2(s12, sB));
        float2 fA = unpack2(dA);
        float2 fB = unpack2(dB);
        float mn = fminf(fminf(fA.x, fA.y), fminf(fB.x, fB.y));

        if (mn < d2 + 1e-3f) {
            // --- exact recompute (verified bit-exact scalar path) ---
            float dv[4];
#pragma unroll
            for (int u = 0; u < 4; ++u) {
                float dot = __fadd_rn(__fadd_rn(__fmul_rn(px, sx[m + u]),
                                                __fmul_rn(py, sy[m + u])),
                                      __fmul_rn(pz, sz[m + u]));
                float d = __fadd_rn(s1, ss[m + u]);
                d = __fsub_rn(d, __fmul_rn(2.0f, dot));
                dv[u] = fmaxf(d, 0.0f);
            }
#pragma unroll
            for (int u = 0; u < 4; ++u) {
                float d = dv[u];
                if (d < d2) {
                    if (d < d1) {
                        if (d < d0) { d2 = d1; i2 = i1; d1 = d0; i1 = i0; d0 = d; i0 = m + u; }
                        else        { d2 = d1; i2 = i1; d1 = d;  i1 = m + u; }
                    } else          { d2 = d;  i2 = m + u; }
                }
            }
        }
    }
    float r0 = __fdiv_rn(1.0f, __fadd_rn(d0, 1e-8f));
    float r1 = __fdiv_rn(1.0f, __fadd_rn(d1, 1e-8f));
    float r2 = __fdiv_rn(1.0f, __fadd_rn(d2, 1e-8f));
    float sum = __fadd_rn(__fadd_rn(r0, r1), r2);
    size_t base = ((size_t)b * NPTS + n) * 4;
    g_w[base + 0] = __fdiv_rn(r0, sum);
    g_w[base + 1] = __fdiv_rn(r1, sum);
    g_w[base + 2] = __fdiv_rn(r2, sum);
    g_w[base + 3] = 0.f;
    g_idx[base + 0] = i0; g_idx[base + 1] = i1; g_idx[base + 2] = i2; g_idx[base + 3] = 0;
}

// ---------------------------------------------------------------------------
// SGEMM 128x128, kTile=32, double-buffered cp.async both operands.
// fma.rn.f32x2 inner loop; per-element accumulation order identical to the
// verified scalar kernel (per-lane rn rounding) -> bit-identical output.
// ---------------------------------------------------------------------------
template <int MODE>
__device__ __forceinline__ void gemm_body(
    const float* __restrict__ AT,          // [K][CCH] transposed weights
    const float* __restrict__ Bp, int ldb, int K,
    const float* __restrict__ bias,
    float* __restrict__ Op, int ldn,
    int n0, int o0, int b)
{
    float (*As)[32][128] = (float(*)[32][128])sm_f;                 // 32KB
    float (*Bs)[32][128] = (float(*)[32][128])(sm_f + 2 * 32 * 128);

    int tid = threadIdx.x;
    int tx = tid & 15;
    int ty = tid >> 4;

    int ck[4], cc[4];
#pragma unroll
    for (int i = 0; i < 4; ++i) {
        int f = tid + 256 * i;
        ck[i] = f >> 5;
        cc[i] = (f & 31) * 4;
    }

    ull acc2[4][8];
#pragma unroll
    for (int i = 0; i < 4; ++i)
#pragma unroll
        for (int j = 0; j < 8; ++j) acc2[i][j] = 0ull;

    // prologue: stage 0
#pragma unroll
    for (int i = 0; i < 4; ++i) {
        cp_async16(&As[0][ck[i]][cc[i]], AT + (size_t)ck[i] * CCH + o0 + cc[i]);
        cp_async16(&Bs[0][ck[i]][cc[i]], Bp + (size_t)ck[i] * ldb + n0 + cc[i]);
    }
    CP_COMMIT();
    CP_WAIT0();
    __syncthreads();

    int cur = 0;
    for (int k0 = 0; k0 < K; k0 += 32) {
        bool nxt = (k0 + 32) < K;
        if (nxt) {
            int nb = cur ^ 1;
#pragma unroll
            for (int i = 0; i < 4; ++i) {
                cp_async16(&As[nb][ck[i]][cc[i]],
                           AT + (size_t)(k0 + 32 + ck[i]) * CCH + o0 + cc[i]);
                cp_async16(&Bs[nb][ck[i]][cc[i]],
                           Bp + (size_t)(k0 + 32 + ck[i]) * ldb + n0 + cc[i]);
            }
            CP_COMMIT();
        }
#pragma unroll
        for (int kk = 0; kk < 32; ++kk) {
            ull aa[4];
            aa[0] = *(const ull*)&As[cur][kk][ty * 4];          // o pair (0,1)
            aa[1] = *(const ull*)&As[cur][kk][ty * 4 + 2];      // o pair (2,3)
            aa[2] = *(const ull*)&As[cur][kk][ty * 4 + 64];     // o pair (4,5)
            aa[3] = *(const ull*)&As[cur][kk][ty * 4 + 66];     // o pair (6,7)
            float4 y0 = *(const float4*)&Bs[cur][kk][tx * 4];
            float4 y1 = *(const float4*)&Bs[cur][kk][tx * 4 + 64];
            ull bb[8];
            bb[0] = pack2(y0.x, y0.x);
            bb[1] = pack2(y0.y, y0.y);
            bb[2] = pack2(y0.z, y0.z);
            bb[3] = pack2(y0.w, y0.w);
            bb[4] = pack2(y1.x, y1.x);
            bb[5] = pack2(y1.y, y1.y);
            bb[6] = pack2(y1.z, y1.z);
            bb[7] = pack2(y1.w, y1.w);
#pragma unroll
            for (int ip = 0; ip < 4; ++ip)
#pragma unroll
                for (int j = 0; j < 8; ++j)
                    ffma2(acc2[ip][j], aa[ip], bb[j]);
        }
        CP_WAIT0();
        __syncthreads();
        cur ^= 1;
    }

    // unpack to scalar acc[i][j]
    float acc[8][8];
#pragma unroll
    for (int ip = 0; ip < 4; ++ip)
#pragma unroll
        for (int j = 0; j < 8; ++j) {
            float2 f = unpack2(acc2[ip][j]);
            acc[2 * ip + 0][j] = f.x;
            acc[2 * ip + 1][j] = f.y;
        }

    if (MODE == 0) {
#pragma unroll
        for (int j = 0; j < 8; ++j) {
            int m = n0 + ((j < 4) ? (tx * 4 + j) : (64 + tx * 4 + (j - 4)));
            size_t base = ((size_t)b * MPTS + m) * CCH + o0 + ty * 4;
            *(float4*)&g_zT[base]      = make_float4(acc[0][j], acc[1][j], acc[2][j], acc[3][j]);
            *(float4*)&g_zT[base + 64] = make_float4(acc[4][j], acc[5][j], acc[6][j], acc[7][j]);
        }
        return;
    }

    if (MODE == 1) {
#pragma unroll
        for (int j = 0; j < 8; ++j) {
            int n = n0 + ((j < 4) ? (tx * 4 + j) : (64 + tx * 4 + (j - 4)));
            size_t wb = ((size_t)b * NPTS + n) * 4;
            float4 w4 = *(const float4*)&g_w[wb];
            int4   i4 = *(const int4*)&g_idx[wb];
            float wk[3] = {w4.x, w4.y, w4.z};
            int   ik[3] = {i4.x, i4.y, i4.z};
#pragma unroll
            for (int t = 0; t < 3; ++t) {
                const float* zp = &g_zT[((size_t)b * MPTS + ik[t]) * CCH + o0 + ty * 4];
                float4 z0 = *(const float4*)zp;
                float4 z1 = *(const float4*)(zp + 64);
                acc[0][j] += wk[t] * z0.x;
                acc[1][j] += wk[t] * z0.y;
                acc[2][j] += wk[t] * z0.z;
                acc[3][j] += wk[t] * z0.w;
                acc[4][j] += wk[t] * z1.x;
                acc[5][j] += wk[t] * z1.y;
                acc[6][j] += wk[t] * z1.z;
                acc[7][j] += wk[t] * z1.w;
            }
        }
    }

#pragma unroll
    for (int i = 0; i < 8; ++i) {
        int o = o0 + ((i < 4) ? (ty * 4 + i) : (64 + ty * 4 + (i - 4)));
        float bv = bias[o];
        float4 v0, v1;
        v0.x = fmaxf(acc[i][0] + bv, 0.0f);
        v0.y = fmaxf(acc[i][1] + bv, 0.0f);
        v0.z = fmaxf(acc[i][2] + bv, 0.0f);
        v0.w = fmaxf(acc[i][3] + bv, 0.0f);
        v1.x = fmaxf(acc[i][4] + bv, 0.0f);
        v1.y = fmaxf(acc[i][5] + bv, 0.0f);
        v1.z = fmaxf(acc[i][6] + bv, 0.0f);
        v1.w = fmaxf(acc[i][7] + bv, 0.0f);
        size_t base = (size_t)o * ldn + n0 + tx * 4;
        *(float4*)&Op[base]      = v0;
        *(float4*)&Op[base + 64] = v1;
    }
}

// ---------------------------------------------------------------------------
// Fused launch: blocks [0,256) do kNN, blocks [256,512) do zGEMM (MODE 0).
// ---------------------------------------------------------------------------
__global__ void __launch_bounds__(256, 2) fused0_kernel(
    const float* __restrict__ p1, const float* __restrict__ p2,
    const float* __restrict__ f2)
{
    int bx = blockIdx.x;
    if (bx < (NPTS / 256) * BB) {
        knn_body(p1, p2, bx & 63, bx >> 6);
    } else {
        int i  = bx - (NPTS / 256) * BB;
        int nt = i & (MPTS / 128 - 1);
        int r  = i >> 5;
        int ot = r & 1;
        int b  = r >> 1;
        gemm_body<0>(g_WT1b, f2 + (size_t)b * CCH * MPTS, MPTS, CCH,
                     nullptr, nullptr, 0, nt * 128, ot * 128, b);
    }
}

__global__ void __launch_bounds__(256, 2) gemm1_kernel(
    const float* __restrict__ f1, const float* __restrict__ b1)
{
    int b = blockIdx.z;
    gemm_body<1>(g_WT1a, f1 + (size_t)b * CCH * NPTS, NPTS, CCH, b1,
                 g_y1 + (size_t)b * CCH * NPTS, NPTS,
                 blockIdx.x * 128, blockIdx.y * 128, b);
}

__global__ void __launch_bounds__(256, 2) gemm2_kernel(
    const float* __restrict__ b2, float* __restrict__ out)
{
    int b = blockIdx.z;
    gemm_body<2>(g_WT2, g_y1 + (size_t)b * CCH * NPTS, NPTS, CCH, b2,
                 out + (size_t)b * CCH * NPTS, NPTS,
                 blockIdx.x * 128, blockIdx.y * 128, b);
}

// ---------------------------------------------------------------------------
extern "C" void kernel_launch(void* const* d_in, const int* in_sizes, int n_in,
                              void* d_out, int out_size)
{
    const float* p1 = (const float*)d_in[0];
    const float* f1 = (const float*)d_in[1];
    const float* p2 = (const float*)d_in[2];
    const float* f2 = (const float*)d_in[3];
    const float* W1 = (const float*)d_in[4];
    const float* b1 = (const float*)d_in[5];
    const float* W2 = (const float*)d_in[6];
    const float* b2 = (const float*)d_in[7];
    float* out = (float*)d_out;

    const int GEMM_SMEM  = 2 * (2 * 32 * 128) * (int)sizeof(float); // 65536
    const int FUSED_SMEM = MPTS * 4 * (int)sizeof(float);           // 65536

    cudaFuncSetAttribute(fused0_kernel, cudaFuncAttributeMaxDynamicSharedMemorySize, FUSED_SMEM);
    cudaFuncSetAttribute(gemm1_kernel,  cudaFuncAttributeMaxDynamicSharedMemorySize, GEMM_SMEM);
    cudaFuncSetAttribute(gemm2_kernel,  cudaFuncAttributeMaxDynamicSharedMemorySize, GEMM_SMEM);

    // 0) transpose weights into [k][o] layout
    transpose_w_kernel<<<CCH, CCH>>>(W1, W2);

    // 1) kNN (256 blocks) + zGEMM (256 blocks) fused
    fused0_kernel<<<512, 256, FUSED_SMEM>>>(p1, p2, f2);

    // 2) y1 = relu(W1[:, 0:C] @ f1 + gather(zT) + b1)
    gemm1_kernel<<<dim3(NPTS / 128, CCH / 128, BB), 256, GEMM_SMEM>>>(f1, b1);

    // 3) out = relu(W2 @ y1 + b2)
    gemm2_kernel<<<dim3(NPTS / 128, CCH / 128, BB), 256, GEMM_SMEM>>>(b2, out);
}